// round 6
// baseline (speedup 1.0000x reference)
#include <cuda_runtime.h>
#include <math.h>

#define NB    16
#define H8    44
#define W8    144
#define HWLO  (H8 * W8)        // 6336
#define NPIX  (NB * HWLO)      // 101376
#define HOUT  (H8 * 8)         // 352
#define WOUT  (W8 * 8)         // 1152
#define P     128              // pixels per CTA (flat-p tiling, 792 CTAs)
#define NCTA  (NPIX / P)       // 792
#define NTHR  256
#define PI_F  3.1415926535f
#define MAX_DEPTH 81.0f

typedef unsigned long long u64;

// ---- dynamic smem layout (float offsets; key arrays 16B-aligned) ----
#define OFF_WT0   0            // [128][64]  8192 f   (broadcast reads -> no padding)
#define OFF_WT1   8192         // [64][32]   2048 f
#define OFF_WT2   10240        // [32][16]   512 f
#define OFF_WT3   10752        // [16][8]    128 f
#define OFF_WT4   10880        // [8][4]     32 f
#define OFF_WC    10912        // [4][3]+pad 16 f
#define OFF_B0    10928        // 64
#define OFF_B1    10992        // 32
#define OFF_B2    11024        // 16
#define OFF_B3    11040        // 8
#define OFF_B4    11048        // 4
#define OFF_BC    11052        // 4
#define OFF_A1S   11056        // [64][128]  8192 f   (byte 44224, 16B aligned)
#define OFF_A2S   19248        // [32][128]  4096 f
#define OFF_PLANE 23344        // [4][128]   512 f    (nx,ny,nz,dist)
#define SMEM_FLOATS 23856
#define SMEM_BYTES  (SMEM_FLOATS * 4)   // 95424 B -> 2 CTAs/SM

// ---------------- packed f32x2 helpers (sm_103a) -------------------------------
__device__ __forceinline__ u64 pack2(float lo, float hi) {
    u64 r; asm("mov.b64 %0, {%1, %2};" : "=l"(r) : "f"(lo), "f"(hi)); return r;
}
__device__ __forceinline__ void unpack2(u64 v, float& lo, float& hi) {
    asm("mov.b64 {%0, %1}, %2;" : "=f"(lo), "=f"(hi) : "l"(v));
}
__device__ __forceinline__ u64 fma2(u64 a, u64 b, u64 c) {
    u64 d; asm("fma.rn.f32x2 %0, %1, %2, %3;" : "=l"(d) : "l"(a), "l"(b), "l"(c));
    return d;
}

__device__ __forceinline__ float eluf(float v) {
    return (v > 0.0f) ? v : (__expf(v) - 1.0f);
}
__device__ __forceinline__ float sigmoidf_fast(float v) {
    return __fdividef(1.0f, 1.0f + __expf(-v));
}

// ---------------------------------- kernel ------------------------------------
__global__ __launch_bounds__(NTHR, 2) void lpg_fused_kernel(
    const float* __restrict__ x,
    const float* __restrict__ w0, const float* __restrict__ b0,
    const float* __restrict__ w1, const float* __restrict__ b1,
    const float* __restrict__ w2, const float* __restrict__ b2,
    const float* __restrict__ w3, const float* __restrict__ b3,
    const float* __restrict__ w4, const float* __restrict__ b4,
    const float* __restrict__ wc, const float* __restrict__ bc,
    float* __restrict__ out)
{
    extern __shared__ float sm[];
    float* wT0 = sm + OFF_WT0;
    float* wT1 = sm + OFF_WT1;
    float* wT2 = sm + OFF_WT2;
    float* wT3 = sm + OFF_WT3;
    float* wT4 = sm + OFF_WT4;
    float* sWc = sm + OFF_WC;
    float* sB0 = sm + OFF_B0;
    float* sB1 = sm + OFF_B1;
    float* sB2 = sm + OFF_B2;
    float* sB3 = sm + OFF_B3;
    float* sB4 = sm + OFF_B4;
    float* sBc = sm + OFF_BC;
    float* a1s = sm + OFF_A1S;    // [64][128]
    float* a2s = sm + OFF_A2S;    // [32][128]
    float* pln = sm + OFF_PLANE;  // [4][128]

    const int t  = threadIdx.x;
    const int p0 = blockIdx.x * P;     // flat pixel base

    // ---- stage weights (transposed [O,C] -> [C,O], no padding) ------------------
    for (int j = t; j < 128 * 64; j += NTHR) { int o = j >> 7, c = j & 127; wT0[c * 64 + o] = w0[j]; }
    for (int j = t; j < 64 * 32;  j += NTHR) { int o = j >> 6, c = j & 63;  wT1[c * 32 + o] = w1[j]; }
    for (int j = t; j < 32 * 16;  j += NTHR) { int o = j >> 5, c = j & 31;  wT2[c * 16 + o] = w2[j]; }
    if (t < 128) { int o = t >> 4, c = t & 15; wT3[c * 8 + o] = w3[t]; }
    if (t < 32)  { int o = t >> 3, c = t & 7;  wT4[c * 4 + o] = w4[t]; }
    if (t < 12)  { int o = t >> 2, c = t & 3;  sWc[c * 3 + o] = wc[t]; }
    if (t < 64) sB0[t] = b0[t];
    if (t < 32) sB1[t] = b1[t];
    if (t < 16) sB2[t] = b2[t];
    if (t < 8)  sB3[t] = b3[t];
    if (t < 4)  sB4[t] = b4[t];
    if (t < 3)  sBc[t] = bc[t];
    __syncthreads();

    const int pg = t & 31;    // 4-pixel group 0..31
    const int og = t >> 5;    // out group 0..7 — warp-uniform

    // 4-pixel group location (never straddles a batch: HWLO % 4 == 0)
    const int pl = 4 * pg;                 // local pixel 0..124
    {
        const int p  = p0 + pl;
        const int bb = p / HWLO;
        const int hw = p - bb * HWLO;
        const float* __restrict__ xp = x + ((size_t)bb * 128) * HWLO + hw;
        const float* __restrict__ wrow = wT0 + og * 8;

        // ---- layer 1: 128 -> 64, fragment = 4 pix x 8 outs -----------------------
        const u64* b0p = (const u64*)sB0;
        u64 acc[4][4];                      // [pixel][out-pair]
#pragma unroll
        for (int j = 0; j < 4; j++) {
            const u64 bv = b0p[og * 4 + j];
            acc[0][j] = bv; acc[1][j] = bv; acc[2][j] = bv; acc[3][j] = bv;
        }
#pragma unroll 4
        for (int c = 0; c < 128; c++) {
            const float4 xv = __ldg((const float4*)(xp + (size_t)c * HWLO));
            const ulonglong2 wa = *(const ulonglong2*)(wrow + c * 64);
            const ulonglong2 wb = *(const ulonglong2*)(wrow + c * 64 + 4);
            const u64 x0 = pack2(xv.x, xv.x), x1 = pack2(xv.y, xv.y);
            const u64 x2 = pack2(xv.z, xv.z), x3 = pack2(xv.w, xv.w);
            acc[0][0] = fma2(wa.x, x0, acc[0][0]); acc[0][1] = fma2(wa.y, x0, acc[0][1]);
            acc[0][2] = fma2(wb.x, x0, acc[0][2]); acc[0][3] = fma2(wb.y, x0, acc[0][3]);
            acc[1][0] = fma2(wa.x, x1, acc[1][0]); acc[1][1] = fma2(wa.y, x1, acc[1][1]);
            acc[1][2] = fma2(wb.x, x1, acc[1][2]); acc[1][3] = fma2(wb.y, x1, acc[1][3]);
            acc[2][0] = fma2(wa.x, x2, acc[2][0]); acc[2][1] = fma2(wa.y, x2, acc[2][1]);
            acc[2][2] = fma2(wb.x, x2, acc[2][2]); acc[2][3] = fma2(wb.y, x2, acc[2][3]);
            acc[3][0] = fma2(wa.x, x3, acc[3][0]); acc[3][1] = fma2(wa.y, x3, acc[3][1]);
            acc[3][2] = fma2(wb.x, x3, acc[3][2]); acc[3][3] = fma2(wb.y, x3, acc[3][3]);
        }
        // ELU + scatter: per out channel, one STS.128 of 4 pixels
#pragma unroll
        for (int j = 0; j < 4; j++) {
            float l0, h0, l1, h1, l2, h2, l3, h3;
            unpack2(acc[0][j], l0, h0); unpack2(acc[1][j], l1, h1);
            unpack2(acc[2][j], l2, h2); unpack2(acc[3][j], l3, h3);
            const int o0 = og * 8 + 2 * j;
            *(float4*)(a1s + o0 * 128 + pl)       = make_float4(eluf(l0), eluf(l1), eluf(l2), eluf(l3));
            *(float4*)(a1s + (o0 + 1) * 128 + pl) = make_float4(eluf(h0), eluf(h1), eluf(h2), eluf(h3));
        }
    }
    __syncthreads();

    // ---- layer 2: 64 -> 32, fragment = 4 pix x 4 outs ---------------------------
    {
        const u64* b1p = (const u64*)sB1;
        const float* __restrict__ wrow = wT1 + og * 4;
        u64 acc[4][2];
#pragma unroll
        for (int j = 0; j < 2; j++) {
            const u64 bv = b1p[og * 2 + j];
            acc[0][j] = bv; acc[1][j] = bv; acc[2][j] = bv; acc[3][j] = bv;
        }
#pragma unroll 4
        for (int c = 0; c < 64; c++) {
            const float4 av = *(const float4*)(a1s + c * 128 + pl);
            const ulonglong2 w = *(const ulonglong2*)(wrow + c * 32);
            const u64 x0 = pack2(av.x, av.x), x1 = pack2(av.y, av.y);
            const u64 x2 = pack2(av.z, av.z), x3 = pack2(av.w, av.w);
            acc[0][0] = fma2(w.x, x0, acc[0][0]); acc[0][1] = fma2(w.y, x0, acc[0][1]);
            acc[1][0] = fma2(w.x, x1, acc[1][0]); acc[1][1] = fma2(w.y, x1, acc[1][1]);
            acc[2][0] = fma2(w.x, x2, acc[2][0]); acc[2][1] = fma2(w.y, x2, acc[2][1]);
            acc[3][0] = fma2(w.x, x3, acc[3][0]); acc[3][1] = fma2(w.y, x3, acc[3][1]);
        }
#pragma unroll
        for (int j = 0; j < 2; j++) {
            float l0, h0, l1, h1, l2, h2, l3, h3;
            unpack2(acc[0][j], l0, h0); unpack2(acc[1][j], l1, h1);
            unpack2(acc[2][j], l2, h2); unpack2(acc[3][j], l3, h3);
            const int o0 = og * 4 + 2 * j;
            *(float4*)(a2s + o0 * 128 + pl)       = make_float4(eluf(l0), eluf(l1), eluf(l2), eluf(l3));
            *(float4*)(a2s + (o0 + 1) * 128 + pl) = make_float4(eluf(h0), eluf(h1), eluf(h2), eluf(h3));
        }
    }
    __syncthreads();

    // ---- tail: one thread per pixel (threads 0..127) ----------------------------
    if (t < P) {
        // layer 3: 32 -> 16
        float a3[16];
        {
            const u64* b2p = (const u64*)sB2;
            u64 acc[8];
#pragma unroll
            for (int j = 0; j < 8; j++) acc[j] = b2p[j];
#pragma unroll 4
            for (int c = 0; c < 32; c++) {
                const float v = a2s[c * 128 + t];
                const u64 xx = pack2(v, v);
                const ulonglong2 wa = *(const ulonglong2*)(wT2 + c * 16);
                const ulonglong2 wb = *(const ulonglong2*)(wT2 + c * 16 + 4);
                const ulonglong2 wc2 = *(const ulonglong2*)(wT2 + c * 16 + 8);
                const ulonglong2 wd = *(const ulonglong2*)(wT2 + c * 16 + 12);
                acc[0] = fma2(wa.x, xx, acc[0]);  acc[1] = fma2(wa.y, xx, acc[1]);
                acc[2] = fma2(wb.x, xx, acc[2]);  acc[3] = fma2(wb.y, xx, acc[3]);
                acc[4] = fma2(wc2.x, xx, acc[4]); acc[5] = fma2(wc2.y, xx, acc[5]);
                acc[6] = fma2(wd.x, xx, acc[6]);  acc[7] = fma2(wd.y, xx, acc[7]);
            }
#pragma unroll
            for (int j = 0; j < 8; j++) {
                float lo, hi; unpack2(acc[j], lo, hi);
                a3[2 * j] = eluf(lo); a3[2 * j + 1] = eluf(hi);
            }
        }
        // layer 4: 16 -> 8
        float a4[8];
        {
            const u64* b3p = (const u64*)sB3;
            u64 acc[4];
#pragma unroll
            for (int j = 0; j < 4; j++) acc[j] = b3p[j];
#pragma unroll
            for (int c = 0; c < 16; c++) {
                const u64 xx = pack2(a3[c], a3[c]);
                const ulonglong2 wa = *(const ulonglong2*)(wT3 + c * 8);
                const ulonglong2 wb = *(const ulonglong2*)(wT3 + c * 8 + 4);
                acc[0] = fma2(wa.x, xx, acc[0]); acc[1] = fma2(wa.y, xx, acc[1]);
                acc[2] = fma2(wb.x, xx, acc[2]); acc[3] = fma2(wb.y, xx, acc[3]);
            }
#pragma unroll
            for (int j = 0; j < 4; j++) {
                float lo, hi; unpack2(acc[j], lo, hi);
                a4[2 * j] = eluf(lo); a4[2 * j + 1] = eluf(hi);
            }
        }
        // layer 5: 8 -> 4 (no activation)
        float a5[4];
        {
            const u64* b4p = (const u64*)sB4;
            u64 acc[2];
            acc[0] = b4p[0]; acc[1] = b4p[1];
#pragma unroll
            for (int c = 0; c < 8; c++) {
                const u64 xx = pack2(a4[c], a4[c]);
                const ulonglong2 w = *(const ulonglong2*)(wT4 + c * 4);
                acc[0] = fma2(w.x, xx, acc[0]); acc[1] = fma2(w.y, xx, acc[1]);
            }
            unpack2(acc[0], a5[0], a5[1]); unpack2(acc[1], a5[2], a5[3]);
        }
        // final 4 -> 3 + plane params
        float y[3];
#pragma unroll
        for (int o = 0; o < 3; o++) {
            float s = sBc[o];
#pragma unroll
            for (int c = 0; c < 4; c++) s += sWc[c * 3 + o] * a5[c];
            y[o] = s;
        }
        const float theta = sigmoidf_fast(y[0]) * (PI_F / 6.0f);
        const float phi   = sigmoidf_fast(y[1]) * (PI_F * 2.0f);
        const float dist  = sigmoidf_fast(y[2]) * MAX_DEPTH;
        const float st = __sinf(theta), ct = __cosf(theta);
        const float sp = __sinf(phi),   cp = __cosf(phi);
        float nx = st * cp, ny = st * sp, nz = ct;
        const float inv = rsqrtf(nx * nx + ny * ny + nz * nz);
        pln[0 * 128 + t] = nx * inv;
        pln[1 * 128 + t] = ny * inv;
        pln[2 * 128 + t] = nz * inv;
        pln[3 * 128 + t] = dist;
    }
    __syncthreads();

    // ---- epilogue: 2 threads per pixel, 4 rows each ------------------------------
    {
        const int px   = t >> 1;       // 0..127
        const int half = t & 1;        // rows 0-3 or 4-7
        const float nx   = pln[0 * 128 + px];
        const float ny   = pln[1 * 128 + px];
        const float nz   = pln[2 * 128 + px];
        const float dist = pln[3 * 128 + px];

        const int p  = p0 + px;
        const int bb = p / HWLO;
        const int hw = p - bb * HWLO;
        const int h  = hw / W8;
        const int w  = hw - h * W8;
        float* __restrict__ op = out + ((size_t)bb * HOUT + (size_t)h * 8) * WOUT + (size_t)w * 8;

#pragma unroll
        for (int r = 0; r < 4; r++) {
            const int i = half * 4 + r;
            const float vterm = ny * ((float)i - 3.5f) * 0.125f + nz;
            float row[8];
#pragma unroll
            for (int j = 0; j < 8; j++) {
                const float u = ((float)j - 3.5f) * 0.125f;
                row[j] = __fdividef(dist, nx * u + vterm);
            }
            float4* o4 = (float4*)(op + (size_t)i * WOUT);
            o4[0] = make_float4(row[0], row[1], row[2], row[3]);
            o4[1] = make_float4(row[4], row[5], row[6], row[7]);
        }
    }
}

extern "C" void kernel_launch(void* const* d_in, const int* in_sizes, int n_in,
                              void* d_out, int out_size) {
    const float* x  = (const float*)d_in[0];
    const float* w0 = (const float*)d_in[1];
    const float* b0 = (const float*)d_in[2];
    const float* w1 = (const float*)d_in[3];
    const float* b1 = (const float*)d_in[4];
    const float* w2 = (const float*)d_in[5];
    const float* b2 = (const float*)d_in[6];
    const float* w3 = (const float*)d_in[7];
    const float* b3 = (const float*)d_in[8];
    const float* w4 = (const float*)d_in[9];
    const float* b4 = (const float*)d_in[10];
    const float* wc = (const float*)d_in[11];
    const float* bc = (const float*)d_in[12];
    float* out = (float*)d_out;

    cudaFuncSetAttribute(lpg_fused_kernel,
                         cudaFuncAttributeMaxDynamicSharedMemorySize, SMEM_BYTES);

    lpg_fused_kernel<<<NCTA, NTHR, SMEM_BYTES>>>(x, w0, b0, w1, b1, w2, b2,
                                                 w3, b3, w4, b4, wc, bc, out);
}